// round 10
// baseline (speedup 1.0000x reference)
#include <cuda_runtime.h>
#include <cuda_bf16.h>
#include <cstdint>

// DWTModelFullBand: reference = 2-level Haar DWT immediately inverted by its
// exact algebraic inverse (idwt2∘dwt2 = identity; stack/reshape is an identity
// permutation). x_rec == x up to ~6e-8 rel err. Irreducible work = 96MB copy.
//
// Steady-state model (R1-R8): dur_us = 192MB / 5.42 TB/s. L2 retains nothing
// across graph replays (full hint matrix tested, all neutral); dur_us is set
// by DRAM drain rate at 68% of spec — classic read/write bus-turnaround loss
// on a finely interleaved 1:1 mix.
//
// R9: coarsen the r/w interleave. Each CTA does a long READ phase (64KB:
// 8 x 32B per thread, front-batched by the scoreboard into one MLP-8 burst)
// then a long WRITE phase (64KB). Per-bank same-direction run length rises
// ~16x, cutting turnaround frequency at the memory controllers.

#define BATCH 8  // 32-byte chunks per thread per phase

struct V8 { uint32_t r[8]; };

__device__ __forceinline__ V8 ld_stream_v8(const void* p) {
    V8 v;
    asm volatile(
        "ld.global.nc.L2::evict_first.v8.b32 {%0,%1,%2,%3,%4,%5,%6,%7}, [%8];"
        : "=r"(v.r[0]), "=r"(v.r[1]), "=r"(v.r[2]), "=r"(v.r[3]),
          "=r"(v.r[4]), "=r"(v.r[5]), "=r"(v.r[6]), "=r"(v.r[7])
        : "l"(p));
    return v;
}

__device__ __forceinline__ void st_stream_v8(void* p, const V8& v) {
    asm volatile(
        "st.global.L2::evict_first.v8.b32 [%0], {%1,%2,%3,%4,%5,%6,%7,%8};"
        :: "l"(p),
           "r"(v.r[0]), "r"(v.r[1]), "r"(v.r[2]), "r"(v.r[3]),
           "r"(v.r[4]), "r"(v.r[5]), "r"(v.r[6]), "r"(v.r[7])
        : "memory");
}

__global__ void __launch_bounds__(256)
dwt_phase_copy_kernel(const char* __restrict__ in,
                      char* __restrict__ out) {
    // Each block owns one contiguous 64KB chunk:
    //   256 threads x BATCH(8) x 32B = 65536 B.
    // Thread t, sub-batch k -> chunk + k*8KB + t*32 (fully coalesced).
    long long base = (long long)blockIdx.x * (256 * 32 * BATCH)
                   + (long long)threadIdx.x * 32;

    V8 v[BATCH];
#pragma unroll
    for (int k = 0; k < BATCH; k++)        // READ phase: 8 loads in flight
        v[k] = ld_stream_v8(in + base + k * (256 * 32));
#pragma unroll
    for (int k = 0; k < BATCH; k++)        // WRITE phase
        st_stream_v8(out + base + k * (256 * 32), v[k]);
}

extern "C" void kernel_launch(void* const* d_in, const int* in_sizes, int n_in,
                              void* d_out, int out_size) {
    const char* x = (const char*)d_in[0];
    char* out = (char*)d_out;

    // 100,663,296 bytes = 1536 x 64KB chunks exactly.
    int blocks = (int)(((long long)out_size * 4) / (256 * 32 * BATCH));  // 1536

    dwt_phase_copy_kernel<<<blocks, 256>>>(x, out);
}

// round 11
// speedup vs baseline: 1.0082x; 1.0082x over previous
#include <cuda_runtime.h>
#include <cuda_bf16.h>

// DWTModelFullBand: reference = 2-level Haar DWT immediately inverted by its
// exact algebraic inverse (idwt2∘dwt2 = identity; stack/reshape is an identity
// permutation). x_rec == x up to ~6e-8 rel err. Irreducible work = 96MB copy.
//
// Steady-state model (R1-R9): dur_us = 192MB / ~5.43 TB/s of DRAM drain,
// pipelined across graph replays; kernel-window time is fully hidden. L2
// retains nothing across replays (hint matrix exhausted) and SM-side phase
// batching can't coarsen the r/w interleave because DRAM writes come from
// LTS-scheduled dirty-line writebacks, not from store submission order.
//
// R10: write-through stores (__stwt). Stores bypass dirty-allocate and
// propagate toward DRAM in submission order — no deferred writeback drain,
// and the controllers see the write stream in the warps' coalesced
// sequential order (the direction-run coarsening R9 attempted, applied at
// the layer where it survives). Loads stay __ldcs (best-measured config).

__global__ void __launch_bounds__(256)
dwt_identity_copy_kernel(const float4* __restrict__ in,
                         float4* __restrict__ out) {
    int i = blockIdx.x * blockDim.x + threadIdx.x;
    float4 v = __ldcs(in + i);   // streaming load
    __stwt(out + i, v);          // write-through: no dirty lines, no deferred writeback
}

extern "C" void kernel_launch(void* const* d_in, const int* in_sizes, int n_in,
                              void* d_out, int out_size) {
    const float4* x = (const float4*)d_in[0];
    float4* out = (float4*)d_out;

    // 25,165,824 floats = 6,291,456 float4 = 24576 blocks x 256 threads exactly.
    int n_vec4 = out_size / 4;
    int threads = 256;
    int blocks = n_vec4 / threads;

    dwt_identity_copy_kernel<<<blocks, threads>>>(x, out);
}